// round 5
// baseline (speedup 1.0000x reference)
#include <cuda_runtime.h>
#include <cstdint>

// ---------------- problem constants ----------------
#define NN 50000
#define EE 800000
#define HH 64
#define RR 8
#define LL 3
#define LN_EPS 1e-5f
#define NEG_SLOPE 0.2f

// ---------------- device scratch ----------------
__device__ float g_h[2 * NN * HH];         // ping-pong node features
__device__ float g_gate[(size_t)NN * 512]; // gate pre-activation
__device__ float g_spre[(size_t)NN * 512]; // att-weighted h sums per (n,r)
__device__ float g_ap[NN * 16];            // attention projections
__device__ float g_exc[EE];                // exp(score) in CSR order
__device__ float g_denom[RR];
__device__ int g_deg[NN];
__device__ int g_off[NN + 1];
__device__ int g_pos[NN];
__device__ int g_csrc[EE];                 // (src<<3)|et in CSR order
__device__ int g_e2c[EE];                  // edge id -> CSR slot

// ---------------- K=64 SGEMM: C[M,64cols] = act(A @ B^T + bias) ----------------
#define AS_STR 132
#define BS_STR 72
#define GEMM_SMEM ((64 * AS_STR + 64 * BS_STR) * 4)

__global__ __launch_bounds__(128)
void gemm64k(const float* __restrict__ A,
             const float* __restrict__ B,
             const float* __restrict__ bias, float* __restrict__ C, int ldc,
             int M, int act)
{
    extern __shared__ float smem[];
    float (*As)[AS_STR] = reinterpret_cast<float (*)[AS_STR]>(smem);
    float (*Bs)[BS_STR] = reinterpret_cast<float (*)[BS_STR]>(smem + 64 * AS_STR);

    const int tid = threadIdx.x;
    const int rowBase = blockIdx.x * 128;
    const int colBase = blockIdx.y * 64;

    #pragma unroll
    for (int i = 0; i < 16; i++) {
        int f = tid + i * 128;
        int r = f >> 4;
        int kq = (f & 15) << 2;
        int gr = rowBase + r;
        float4 v = make_float4(0.f, 0.f, 0.f, 0.f);
        if (gr < M) v = *reinterpret_cast<const float4*>(A + (size_t)gr * 64 + kq);
        As[kq + 0][r] = v.x; As[kq + 1][r] = v.y; As[kq + 2][r] = v.z; As[kq + 3][r] = v.w;
    }
    #pragma unroll
    for (int i = 0; i < 8; i++) {
        int f = tid + i * 128;
        int j = f >> 4;
        int kq = (f & 15) << 2;
        float4 v = *reinterpret_cast<const float4*>(B + (size_t)(colBase + j) * 64 + kq);
        Bs[kq + 0][j] = v.x; Bs[kq + 1][j] = v.y; Bs[kq + 2][j] = v.z; Bs[kq + 3][j] = v.w;
    }
    __syncthreads();

    const int tx = tid & 7;
    const int ty = tid >> 3;

    unsigned long long acc[8][4];
    #pragma unroll
    for (int i = 0; i < 8; i++)
        #pragma unroll
        for (int j = 0; j < 4; j++) acc[i][j] = 0ULL;

    #pragma unroll
    for (int k = 0; k < 64; k++) {
        const float4* ap = reinterpret_cast<const float4*>(&As[k][ty * 8]);
        float4 a03 = ap[0], a47 = ap[1];
        float a[8] = {a03.x, a03.y, a03.z, a03.w, a47.x, a47.y, a47.z, a47.w};
        const ulonglong2* bp = reinterpret_cast<const ulonglong2*>(&Bs[k][tx * 8]);
        ulonglong2 bb0 = bp[0], bb1 = bp[1];
        unsigned long long b2[4] = {bb0.x, bb0.y, bb1.x, bb1.y};
        #pragma unroll
        for (int i = 0; i < 8; i++) {
            unsigned long long a2;
            asm("mov.b64 %0, {%1, %1};" : "=l"(a2) : "f"(a[i]));
            #pragma unroll
            for (int j = 0; j < 4; j++)
                asm("fma.rn.f32x2 %0, %1, %2, %0;" : "+l"(acc[i][j]) : "l"(a2), "l"(b2[j]));
        }
    }

    #pragma unroll
    for (int i = 0; i < 8; i++) {
        int gr = rowBase + ty * 8 + i;
        if (gr >= M) continue;
        #pragma unroll
        for (int j = 0; j < 4; j++) {
            float lo, hi;
            asm("mov.b64 {%0, %1}, %2;" : "=f"(lo), "=f"(hi) : "l"(acc[i][j]));
            int col = colBase + tx * 8 + 2 * j;
            if (bias) { lo += bias[col]; hi += bias[col + 1]; }
            if (act == 1) { lo = fmaxf(lo, 0.f); hi = fmaxf(hi, 0.f); }
            *reinterpret_cast<float2*>(C + (size_t)gr * ldc + col) = make_float2(lo, hi);
        }
    }
}

// ============ fused: batched (spre @ W_rel^T) * sigmoid(gate+b) mean + residual + LN + relu ============
// one block = 128 nodes, loops over all 8 relations; writes h_next directly.
__global__ __launch_bounds__(128)
void relcomb_k(const float* __restrict__ hin, float* __restrict__ hout,
               const float* __restrict__ W_rel, const float* __restrict__ b_gate,
               const float* __restrict__ gamma, const float* __restrict__ beta)
{
    extern __shared__ float smem[];
    float (*Ss)[AS_STR] = reinterpret_cast<float (*)[AS_STR]>(smem);
    float (*Bs)[BS_STR] = reinterpret_cast<float (*)[BS_STR]>(smem + 64 * AS_STR);

    const int tid = threadIdx.x;
    const int tx = tid & 7;
    const int ty = tid >> 3;
    const int rowBase = blockIdx.x * 128;

    float hacc[8][8];
    #pragma unroll
    for (int i = 0; i < 8; i++)
        #pragma unroll
        for (int j = 0; j < 8; j++) hacc[i][j] = 0.f;

    for (int r = 0; r < RR; r++) {
        // stage spre r-slice [128 rows x 64 k] transposed
        #pragma unroll
        for (int i = 0; i < 16; i++) {
            int f = tid + i * 128;
            int row = f >> 4;
            int kq = (f & 15) << 2;
            int gr = rowBase + row;
            float4 v = make_float4(0.f, 0.f, 0.f, 0.f);
            if (gr < NN) v = *reinterpret_cast<const float4*>(&g_spre[(size_t)gr * 512 + r * 64 + kq]);
            Ss[kq + 0][row] = v.x; Ss[kq + 1][row] = v.y; Ss[kq + 2][row] = v.z; Ss[kq + 3][row] = v.w;
        }
        // stage W_rel[r] [64 x 64]
        #pragma unroll
        for (int i = 0; i < 8; i++) {
            int f = tid + i * 128;
            int j = f >> 4;
            int kq = (f & 15) << 2;
            float4 v = *reinterpret_cast<const float4*>(W_rel + (size_t)r * 4096 + j * 64 + kq);
            Bs[kq + 0][j] = v.x; Bs[kq + 1][j] = v.y; Bs[kq + 2][j] = v.z; Bs[kq + 3][j] = v.w;
        }
        __syncthreads();

        unsigned long long pr[8][4];
        #pragma unroll
        for (int i = 0; i < 8; i++)
            #pragma unroll
            for (int j = 0; j < 4; j++) pr[i][j] = 0ULL;

        #pragma unroll
        for (int k = 0; k < 64; k++) {
            const float4* ap = reinterpret_cast<const float4*>(&Ss[k][ty * 8]);
            float4 a03 = ap[0], a47 = ap[1];
            float a[8] = {a03.x, a03.y, a03.z, a03.w, a47.x, a47.y, a47.z, a47.w};
            const ulonglong2* bp = reinterpret_cast<const ulonglong2*>(&Bs[k][tx * 8]);
            ulonglong2 bb0 = bp[0], bb1 = bp[1];
            unsigned long long b2[4] = {bb0.x, bb0.y, bb1.x, bb1.y};
            #pragma unroll
            for (int i = 0; i < 8; i++) {
                unsigned long long a2;
                asm("mov.b64 %0, {%1, %1};" : "=l"(a2) : "f"(a[i]));
                #pragma unroll
                for (int j = 0; j < 4; j++)
                    asm("fma.rn.f32x2 %0, %1, %2, %0;" : "+l"(pr[i][j]) : "l"(a2), "l"(b2[j]));
            }
        }
        __syncthreads();   // before restaging next r

        // apply gate for this r: hacc += sigmoid(gate+b) * prod
        #pragma unroll
        for (int i = 0; i < 8; i++) {
            int gr = rowBase + ty * 8 + i;
            if (gr >= NN) continue;
            const float* grow = &g_gate[(size_t)gr * 512 + r * 64 + tx * 8];
            const float* brow = &b_gate[r * 64 + tx * 8];
            #pragma unroll
            for (int j = 0; j < 4; j++) {
                float plo, phi;
                asm("mov.b64 {%0, %1}, %2;" : "=f"(plo), "=f"(phi) : "l"(pr[i][j]));
                float2 gp = *reinterpret_cast<const float2*>(grow + 2 * j);
                float2 bg = *reinterpret_cast<const float2*>(brow + 2 * j);
                float slo = 1.f / (1.f + __expf(-(gp.x + bg.x)));
                float shi = 1.f / (1.f + __expf(-(gp.y + bg.y)));
                hacc[i][2 * j]     += slo * plo;
                hacc[i][2 * j + 1] += shi * phi;
            }
        }
    }

    // mean over r + residual + LayerNorm + relu; reduction over tx (8 lanes) via shfl
    #pragma unroll
    for (int i = 0; i < 8; i++) {
        int gr = rowBase + ty * 8 + i;
        float hv[8];
        if (gr < NN) {
            #pragma unroll
            for (int j = 0; j < 4; j++) {
                float2 h2 = *reinterpret_cast<const float2*>(&hin[(size_t)gr * 64 + tx * 8 + 2 * j]);
                hv[2 * j]     = h2.x + hacc[i][2 * j] * 0.125f;
                hv[2 * j + 1] = h2.y + hacc[i][2 * j + 1] * 0.125f;
            }
        } else {
            #pragma unroll
            for (int j = 0; j < 8; j++) hv[j] = 0.f;
        }
        float s = 0.f;
        #pragma unroll
        for (int j = 0; j < 8; j++) s += hv[j];
        #pragma unroll
        for (int o = 1; o < 8; o <<= 1) s += __shfl_xor_sync(0xffffffffu, s, o);
        float mu = s * (1.f / 64.f);
        float v = 0.f;
        #pragma unroll
        for (int j = 0; j < 8; j++) { float d = hv[j] - mu; v += d * d; }
        #pragma unroll
        for (int o = 1; o < 8; o <<= 1) v += __shfl_xor_sync(0xffffffffu, v, o);
        float rs = rsqrtf(v * (1.f / 64.f) + LN_EPS);
        if (gr < NN) {
            #pragma unroll
            for (int j = 0; j < 4; j++) {
                int col = tx * 8 + 2 * j;
                float o1 = (hv[2 * j] - mu) * rs * gamma[col] + beta[col];
                float o2 = (hv[2 * j + 1] - mu) * rs * gamma[col + 1] + beta[col + 1];
                *reinterpret_cast<float2*>(&hout[(size_t)gr * 64 + col]) =
                    make_float2(fmaxf(o1, 0.f), fmaxf(o2, 0.f));
            }
        }
    }
}

// ---------------- CSR build ----------------
__global__ __launch_bounds__(256)
void zerodeg_k()
{
    int i = blockIdx.x * 256 + threadIdx.x;
    if (i < NN) g_deg[i] = 0;
}

__global__ __launch_bounds__(256)
void hist_k(const int* __restrict__ ei)
{
    int e = blockIdx.x * 256 + threadIdx.x;
    if (e < EE) atomicAdd(&g_deg[ei[EE + e]], 1);
}

__global__ __launch_bounds__(1024)
void scan_k()
{
    __shared__ int s[1024];
    __shared__ int carry_s;
    int tid = threadIdx.x;
    if (tid == 0) carry_s = 0;
    __syncthreads();
    for (int base = 0; base < NN; base += 4096) {
        int i0 = base + tid * 4;
        int v0 = (i0 + 0 < NN) ? g_deg[i0 + 0] : 0;
        int v1 = (i0 + 1 < NN) ? g_deg[i0 + 1] : 0;
        int v2 = (i0 + 2 < NN) ? g_deg[i0 + 2] : 0;
        int v3 = (i0 + 3 < NN) ? g_deg[i0 + 3] : 0;
        int tsum = v0 + v1 + v2 + v3;
        int val = tsum;
        s[tid] = val;
        __syncthreads();
        #pragma unroll
        for (int off = 1; off < 1024; off <<= 1) {
            int t = (tid >= off) ? s[tid - off] : 0;
            __syncthreads();
            val += t;
            s[tid] = val;
            __syncthreads();
        }
        int carry = carry_s;
        int o0 = carry + val - tsum;
        int o1 = o0 + v0, o2 = o1 + v1, o3 = o2 + v2;
        if (i0 + 0 < NN) { g_off[i0 + 0] = o0; g_pos[i0 + 0] = o0; }
        if (i0 + 1 < NN) { g_off[i0 + 1] = o1; g_pos[i0 + 1] = o1; }
        if (i0 + 2 < NN) { g_off[i0 + 2] = o2; g_pos[i0 + 2] = o2; }
        if (i0 + 3 < NN) { g_off[i0 + 3] = o3; g_pos[i0 + 3] = o3; }
        __syncthreads();
        if (tid == 1023) carry_s = carry + val;
        __syncthreads();
    }
    if (tid == 0) g_off[NN] = EE;
}

__global__ __launch_bounds__(256)
void fill_k(const int* __restrict__ ei, const int* __restrict__ et)
{
    int e = blockIdx.x * 256 + threadIdx.x;
    if (e >= EE) return;
    int dst = ei[EE + e];
    int p = atomicAdd(&g_pos[dst], 1);
    g_csrc[p] = (ei[e] << 3) | et[e];
    g_e2c[e] = p;
}

// ---------------- attention projections ----------------
__global__ __launch_bounds__(256)
void attproj_k(const float* __restrict__ h, const float* __restrict__ W_att)
{
    __shared__ float hs[16][65];
    __shared__ float ws[16][65];
    int tid = threadIdx.x;
    int nodeBase = blockIdx.x * 16;
    for (int i = tid; i < 16 * 64; i += 256) {
        int o = i >> 6, c = i & 63;
        ws[o][c] = W_att[(o & 7) * 128 + ((o >> 3) << 6) + c];
        int n = nodeBase + o;
        hs[o][c] = (n < NN) ? h[n * 64 + c] : 0.f;
    }
    __syncthreads();
    int nd = tid >> 4, o = tid & 15;
    float s = 0.f;
    #pragma unroll
    for (int c = 0; c < 64; c++) s += hs[nd][c] * ws[o][c];
    int n = nodeBase + nd;
    if (n < NN) g_ap[n * 16 + o] = s;
    if (blockIdx.x == 0 && tid < RR) g_denom[tid] = 0.f;
}

// ---------------- fused scores + exp + denom (segment-max dropped: shift-invariant) ----
__global__ __launch_bounds__(256)
void scoreexp_k(const int* __restrict__ ei, const int* __restrict__ et,
                const float* __restrict__ b_att)
{
    __shared__ float ssum[RR];
    int tid = threadIdx.x;
    if (tid < RR) ssum[tid] = 0.f;
    __syncthreads();
    int e = blockIdx.x * 256 + tid;
    if (e < EE) {
        int t = et[e];
        int s = ei[e], d = ei[EE + e];
        float sc = g_ap[s * 16 + t] + g_ap[d * 16 + 8 + t] + b_att[t];
        sc = (sc > 0.f) ? sc : NEG_SLOPE * sc;
        float ex = __expf(sc);
        g_exc[g_e2c[e]] = ex;
        atomicAdd(&ssum[t], ex);
    }
    __syncthreads();
    if (tid < RR) atomicAdd(&g_denom[tid], ssum[tid]);
}

// ---------------- aggregate att-weighted h[src] per (dst, r) ----------------
__global__ __launch_bounds__(256)
void aggscatter_k(const float* __restrict__ h)
{
    __shared__ float sden[RR];
    int tid = threadIdx.x;
    if (tid < RR) sden[tid] = 1.f / g_denom[tid];
    __syncthreads();

    int warp = tid >> 5, lane = tid & 31;
    int n = blockIdx.x * 8 + warp;
    if (n >= NN) return;

    float2 acc[8];
    #pragma unroll
    for (int r = 0; r < 8; r++) acc[r] = make_float2(0.f, 0.f);

    int beg = g_off[n], end = g_off[n + 1];
    for (int b = beg; b < end; b += 4) {
        int pk[4]; float at[4];
        #pragma unroll
        for (int i = 0; i < 4; i++) {
            int j = b + i;
            int jc = (j < end) ? j : beg;
            pk[i] = g_csrc[jc];
            float ex = g_exc[jc];
            at[i] = (j < end) ? ex * sden[pk[i] & 7] : 0.f;
        }
        float2 v[4];
        #pragma unroll
        for (int i = 0; i < 4; i++)
            v[i] = *reinterpret_cast<const float2*>(&h[(pk[i] >> 3) * 64 + lane * 2]);
        #pragma unroll
        for (int i = 0; i < 4; i++) {
            int er = pk[i] & 7;
            #pragma unroll
            for (int r = 0; r < 8; r++)
                if (er == r) { acc[r].x += at[i] * v[i].x; acc[r].y += at[i] * v[i].y; }
        }
    }

    size_t base = (size_t)n * 512;
    #pragma unroll
    for (int r = 0; r < 8; r++)
        *reinterpret_cast<float2*>(&g_spre[base + r * 64 + lane * 2]) = acc[r];
}

// ---------------- launch ----------------
extern "C" void kernel_launch(void* const* d_in, const int* in_sizes, int n_in,
                              void* d_out, int out_size)
{
    const float* x      = (const float*)d_in[0];
    const int*   ei     = (const int*)  d_in[1];
    const int*   et     = (const int*)  d_in[2];
    const float* W_in   = (const float*)d_in[3];
    const float* b_in   = (const float*)d_in[4];
    const float* W_rel  = (const float*)d_in[5];
    const float* W_gate = (const float*)d_in[6];
    const float* b_gate = (const float*)d_in[7];
    const float* W_att  = (const float*)d_in[8];
    const float* b_att  = (const float*)d_in[9];
    const float* ln_g   = (const float*)d_in[10];
    const float* ln_b   = (const float*)d_in[11];
    const float* W_out  = (const float*)d_in[12];
    const float* b_out  = (const float*)d_in[13];
    float* out = (float*)d_out;

    float *hbuf, *gatep;
    cudaGetSymbolAddress((void**)&hbuf,  g_h);
    cudaGetSymbolAddress((void**)&gatep, g_gate);
    float* h0p = hbuf;
    float* h1p = hbuf + (size_t)NN * HH;

    cudaFuncSetAttribute(gemm64k,   cudaFuncAttributeMaxDynamicSharedMemorySize, GEMM_SMEM);
    cudaFuncSetAttribute(relcomb_k, cudaFuncAttributeMaxDynamicSharedMemorySize, GEMM_SMEM);

    // CSR over dst (built once; reused across layers)
    zerodeg_k<<<(NN + 255) / 256, 256>>>();
    hist_k<<<(EE + 255) / 256, 256>>>(ei);
    scan_k<<<1, 1024>>>();
    fill_k<<<(EE + 255) / 256, 256>>>(ei, et);

    // input projection
    gemm64k<<<dim3((NN + 127) / 128, 1), 128, GEMM_SMEM>>>(x, W_in, b_in, h0p, 64, NN, 1);

    float* hc = h0p;
    float* hn = h1p;
    for (int layer = 0; layer < LL; layer++) {
        gemm64k<<<dim3((NN + 127) / 128, 8), 128, GEMM_SMEM>>>(hc, W_gate, nullptr, gatep, 512, NN, 0);
        attproj_k<<<(NN + 15) / 16, 256>>>(hc, W_att);
        scoreexp_k<<<(EE + 255) / 256, 256>>>(ei, et, b_att);
        aggscatter_k<<<(NN + 7) / 8, 256>>>(hc);
        relcomb_k<<<(NN + 127) / 128, 128, GEMM_SMEM>>>(hc, hn, W_rel, b_gate,
                                                        ln_g + layer * 64, ln_b + layer * 64);
        float* tmp = hc; hc = hn; hn = tmp;
    }

    gemm64k<<<dim3((NN + 127) / 128, 1), 128, GEMM_SMEM>>>(hc, W_out, b_out, out, 64, NN, 0);
}

// round 7
// speedup vs baseline: 1.2128x; 1.2128x over previous
#include <cuda_runtime.h>
#include <cstdint>

// ---------------- problem constants ----------------
#define NN 50000
#define EE 800000
#define HH 64
#define RR 8
#define LL 3
#define LN_EPS 1e-5f
#define NEG_SLOPE 0.2f

// ---------------- device scratch ----------------
__device__ float g_h[2 * NN * HH];         // ping-pong node features
__device__ float g_prod[(size_t)NN * 512]; // gated relgemm output
__device__ float g_gate[(size_t)NN * 512]; // sigmoid(gate + b_gate)
__device__ float g_spre[(size_t)NN * 512]; // att-weighted h sums per (n,r)
__device__ float g_ap[NN * 16];            // attention projections
__device__ float g_exc[EE];                // exp(score) in CSR order
__device__ float g_denom[RR];
__device__ int g_deg[NN];
__device__ int g_off[NN + 1];
__device__ int g_pos[NN];
__device__ int g_csrc[EE];                 // (src<<3)|et in CSR order
__device__ int g_e2c[EE];                  // edge id -> CSR slot

// ---------------- K=64 SGEMM ----------------
// act: 0=none, 1=relu, 2=sigmoid.  gmul: multiply epilogue by g_gate[gr*512+col].
#define AS_STR 132
#define BS_STR 72
#define GEMM_SMEM ((64 * AS_STR + 64 * BS_STR) * 4)

__global__ __launch_bounds__(128)
void gemm64k(const float* __restrict__ A, int lda,
             const float* __restrict__ B,
             const float* __restrict__ bias, float* __restrict__ C, int ldc,
             int M, int batched, int act, int gmul)
{
    extern __shared__ float smem[];
    float (*As)[AS_STR] = reinterpret_cast<float (*)[AS_STR]>(smem);
    float (*Bs)[BS_STR] = reinterpret_cast<float (*)[BS_STR]>(smem + 64 * AS_STR);

    const int tid = threadIdx.x;
    const int rowBase = blockIdx.x * 128;
    const int colBase = blockIdx.y * 64;
    const int aoff = batched ? colBase : 0;

    #pragma unroll
    for (int i = 0; i < 16; i++) {
        int f = tid + i * 128;
        int r = f >> 4;
        int kq = (f & 15) << 2;
        int gr = rowBase + r;
        float4 v = make_float4(0.f, 0.f, 0.f, 0.f);
        if (gr < M) v = *reinterpret_cast<const float4*>(A + (size_t)gr * lda + aoff + kq);
        As[kq + 0][r] = v.x; As[kq + 1][r] = v.y; As[kq + 2][r] = v.z; As[kq + 3][r] = v.w;
    }
    #pragma unroll
    for (int i = 0; i < 8; i++) {
        int f = tid + i * 128;
        int j = f >> 4;
        int kq = (f & 15) << 2;
        const float* brow = batched ? (B + (size_t)colBase * 64 + j * 64)
                                    : (B + (size_t)(colBase + j) * 64);
        float4 v = *reinterpret_cast<const float4*>(brow + kq);
        Bs[kq + 0][j] = v.x; Bs[kq + 1][j] = v.y; Bs[kq + 2][j] = v.z; Bs[kq + 3][j] = v.w;
    }
    __syncthreads();

    const int tx = tid & 7;
    const int ty = tid >> 3;

    unsigned long long acc[8][4];
    #pragma unroll
    for (int i = 0; i < 8; i++)
        #pragma unroll
        for (int j = 0; j < 4; j++) acc[i][j] = 0ULL;

    #pragma unroll
    for (int k = 0; k < 64; k++) {
        const float4* ap = reinterpret_cast<const float4*>(&As[k][ty * 8]);
        float4 a03 = ap[0], a47 = ap[1];
        float a[8] = {a03.x, a03.y, a03.z, a03.w, a47.x, a47.y, a47.z, a47.w};
        const ulonglong2* bp = reinterpret_cast<const ulonglong2*>(&Bs[k][tx * 8]);
        ulonglong2 bb0 = bp[0], bb1 = bp[1];
        unsigned long long b2[4] = {bb0.x, bb0.y, bb1.x, bb1.y};
        #pragma unroll
        for (int i = 0; i < 8; i++) {
            unsigned long long a2;
            asm("mov.b64 %0, {%1, %1};" : "=l"(a2) : "f"(a[i]));
            #pragma unroll
            for (int j = 0; j < 4; j++)
                asm("fma.rn.f32x2 %0, %1, %2, %0;" : "+l"(acc[i][j]) : "l"(a2), "l"(b2[j]));
        }
    }

    #pragma unroll
    for (int i = 0; i < 8; i++) {
        int gr = rowBase + ty * 8 + i;
        if (gr >= M) continue;
        #pragma unroll
        for (int j = 0; j < 4; j++) {
            float lo, hi;
            asm("mov.b64 {%0, %1}, %2;" : "=f"(lo), "=f"(hi) : "l"(acc[i][j]));
            int col = colBase + tx * 8 + 2 * j;
            if (bias) { lo += bias[col]; hi += bias[col + 1]; }
            if (act == 1) { lo = fmaxf(lo, 0.f); hi = fmaxf(hi, 0.f); }
            else if (act == 2) {
                lo = 1.f / (1.f + __expf(-lo));
                hi = 1.f / (1.f + __expf(-hi));
            }
            if (gmul) {
                float2 sg = *reinterpret_cast<const float2*>(&g_gate[(size_t)gr * 512 + col]);
                lo *= sg.x; hi *= sg.y;
            }
            *reinterpret_cast<float2*>(C + (size_t)gr * ldc + col) = make_float2(lo, hi);
        }
    }
}

// ---------------- CSR build ----------------
__global__ __launch_bounds__(256)
void zerodeg_k()
{
    int i = blockIdx.x * 256 + threadIdx.x;
    if (i < NN) g_deg[i] = 0;
}

__global__ __launch_bounds__(256)
void hist_k(const int* __restrict__ ei)
{
    int e = blockIdx.x * 256 + threadIdx.x;
    if (e < EE) atomicAdd(&g_deg[ei[EE + e]], 1);
}

__global__ __launch_bounds__(1024)
void scan_k()
{
    __shared__ int s[1024];
    __shared__ int carry_s;
    int tid = threadIdx.x;
    if (tid == 0) carry_s = 0;
    __syncthreads();
    for (int base = 0; base < NN; base += 4096) {
        int i0 = base + tid * 4;
        int v0 = (i0 + 0 < NN) ? g_deg[i0 + 0] : 0;
        int v1 = (i0 + 1 < NN) ? g_deg[i0 + 1] : 0;
        int v2 = (i0 + 2 < NN) ? g_deg[i0 + 2] : 0;
        int v3 = (i0 + 3 < NN) ? g_deg[i0 + 3] : 0;
        int tsum = v0 + v1 + v2 + v3;
        int val = tsum;
        s[tid] = val;
        __syncthreads();
        #pragma unroll
        for (int off = 1; off < 1024; off <<= 1) {
            int t = (tid >= off) ? s[tid - off] : 0;
            __syncthreads();
            val += t;
            s[tid] = val;
            __syncthreads();
        }
        int carry = carry_s;
        int o0 = carry + val - tsum;
        int o1 = o0 + v0, o2 = o1 + v1, o3 = o2 + v2;
        if (i0 + 0 < NN) { g_off[i0 + 0] = o0; g_pos[i0 + 0] = o0; }
        if (i0 + 1 < NN) { g_off[i0 + 1] = o1; g_pos[i0 + 1] = o1; }
        if (i0 + 2 < NN) { g_off[i0 + 2] = o2; g_pos[i0 + 2] = o2; }
        if (i0 + 3 < NN) { g_off[i0 + 3] = o3; g_pos[i0 + 3] = o3; }
        __syncthreads();
        if (tid == 1023) carry_s = carry + val;
        __syncthreads();
    }
    if (tid == 0) g_off[NN] = EE;
}

__global__ __launch_bounds__(256)
void fill_k(const int* __restrict__ ei, const int* __restrict__ et)
{
    int e = blockIdx.x * 256 + threadIdx.x;
    if (e >= EE) return;
    int dst = ei[EE + e];
    int p = atomicAdd(&g_pos[dst], 1);
    g_csrc[p] = (ei[e] << 3) | et[e];
    g_e2c[e] = p;
}

// ---------------- attention projections ----------------
__global__ __launch_bounds__(256)
void attproj_k(const float* __restrict__ h, const float* __restrict__ W_att)
{
    __shared__ float hs[16][65];
    __shared__ float ws[16][65];
    int tid = threadIdx.x;
    int nodeBase = blockIdx.x * 16;
    for (int i = tid; i < 16 * 64; i += 256) {
        int o = i >> 6, c = i & 63;
        ws[o][c] = W_att[(o & 7) * 128 + ((o >> 3) << 6) + c];
        int n = nodeBase + o;
        hs[o][c] = (n < NN) ? h[n * 64 + c] : 0.f;
    }
    __syncthreads();
    int nd = tid >> 4, o = tid & 15;
    float s = 0.f;
    #pragma unroll
    for (int c = 0; c < 64; c++) s += hs[nd][c] * ws[o][c];
    int n = nodeBase + nd;
    if (n < NN) g_ap[n * 16 + o] = s;
    if (blockIdx.x == 0 && tid < RR) g_denom[tid] = 0.f;
}

// ---------------- fused scores + exp + denom (shift-invariant, no segment max) ----
__global__ __launch_bounds__(256)
void scoreexp_k(const int* __restrict__ ei, const int* __restrict__ et,
                const float* __restrict__ b_att)
{
    __shared__ float ssum[RR];
    int tid = threadIdx.x;
    if (tid < RR) ssum[tid] = 0.f;
    __syncthreads();
    int e = blockIdx.x * 256 + tid;
    if (e < EE) {
        int t = et[e];
        int s = ei[e], d = ei[EE + e];
        float sc = g_ap[s * 16 + t] + g_ap[d * 16 + 8 + t] + b_att[t];
        sc = (sc > 0.f) ? sc : NEG_SLOPE * sc;
        float ex = __expf(sc);
        g_exc[g_e2c[e]] = ex;
        atomicAdd(&ssum[t], ex);
    }
    __syncthreads();
    if (tid < RR) atomicAdd(&g_denom[tid], ssum[tid]);
}

// ---------------- aggregate att-weighted h[src] per (dst, r) ----------------
__global__ __launch_bounds__(256)
void aggscatter_k(const float* __restrict__ h)
{
    __shared__ float sden[RR];
    int tid = threadIdx.x;
    if (tid < RR) sden[tid] = 1.f / g_denom[tid];
    __syncthreads();

    int warp = tid >> 5, lane = tid & 31;
    int n = blockIdx.x * 8 + warp;
    if (n >= NN) return;

    float2 acc[8];
    #pragma unroll
    for (int r = 0; r < 8; r++) acc[r] = make_float2(0.f, 0.f);

    int beg = g_off[n], end = g_off[n + 1];
    for (int b = beg; b < end; b += 4) {
        int pk[4]; float at[4];
        #pragma unroll
        for (int i = 0; i < 4; i++) {
            int j = b + i;
            int jc = (j < end) ? j : beg;
            pk[i] = g_csrc[jc];
            float ex = g_exc[jc];
            at[i] = (j < end) ? ex * sden[pk[i] & 7] : 0.f;
        }
        float2 v[4];
        #pragma unroll
        for (int i = 0; i < 4; i++)
            v[i] = *reinterpret_cast<const float2*>(&h[(pk[i] >> 3) * 64 + lane * 2]);
        #pragma unroll
        for (int i = 0; i < 4; i++) {
            int er = pk[i] & 7;
            #pragma unroll
            for (int r = 0; r < 8; r++)
                if (er == r) { acc[r].x += at[i] * v[i].x; acc[r].y += at[i] * v[i].y; }
        }
    }

    size_t base = (size_t)n * 512;
    #pragma unroll
    for (int r = 0; r < 8; r++)
        *reinterpret_cast<float2*>(&g_spre[base + r * 64 + lane * 2]) = acc[r];
}

// ---------------- mean of gated prod + residual + LN + relu ----------------
__global__ __launch_bounds__(256)
void combine_k(const float* __restrict__ hin, float* __restrict__ hout,
               const float* __restrict__ gamma, const float* __restrict__ beta)
{
    int tid = threadIdx.x;
    int warp = tid >> 5, lane = tid & 31;
    int n = blockIdx.x * 8 + warp;
    if (n >= NN) return;

    size_t base = (size_t)n * 512;
    float hx = 0.f, hy = 0.f;
    #pragma unroll
    for (int r = 0; r < 8; r++) {
        float2 pv = *reinterpret_cast<const float2*>(&g_prod[base + r * 64 + lane * 2]);
        hx += pv.x;
        hy += pv.y;
    }
    float2 hv = *reinterpret_cast<const float2*>(&hin[n * 64 + lane * 2]);
    float h1 = hv.x + hx * 0.125f;
    float h2 = hv.y + hy * 0.125f;

    float s = h1 + h2;
    #pragma unroll
    for (int o = 16; o > 0; o >>= 1) s += __shfl_xor_sync(0xffffffffu, s, o);
    float mu = s * (1.f / 64.f);
    float d1 = h1 - mu, d2 = h2 - mu;
    float v = d1 * d1 + d2 * d2;
    #pragma unroll
    for (int o = 16; o > 0; o >>= 1) v += __shfl_xor_sync(0xffffffffu, v, o);
    float rs = rsqrtf(v * (1.f / 64.f) + LN_EPS);
    float o1 = d1 * rs * gamma[lane * 2] + beta[lane * 2];
    float o2 = d2 * rs * gamma[lane * 2 + 1] + beta[lane * 2 + 1];
    *reinterpret_cast<float2*>(&hout[n * 64 + lane * 2]) =
        make_float2(fmaxf(o1, 0.f), fmaxf(o2, 0.f));
}

// ---------------- launch ----------------
extern "C" void kernel_launch(void* const* d_in, const int* in_sizes, int n_in,
                              void* d_out, int out_size)
{
    const float* x      = (const float*)d_in[0];
    const int*   ei     = (const int*)  d_in[1];
    const int*   et     = (const int*)  d_in[2];
    const float* W_in   = (const float*)d_in[3];
    const float* b_in   = (const float*)d_in[4];
    const float* W_rel  = (const float*)d_in[5];
    const float* W_gate = (const float*)d_in[6];
    const float* b_gate = (const float*)d_in[7];
    const float* W_att  = (const float*)d_in[8];
    const float* b_att  = (const float*)d_in[9];
    const float* ln_g   = (const float*)d_in[10];
    const float* ln_b   = (const float*)d_in[11];
    const float* W_out  = (const float*)d_in[12];
    const float* b_out  = (const float*)d_in[13];
    float* out = (float*)d_out;

    float *hbuf, *sprep, *gatep, *prodp;
    cudaGetSymbolAddress((void**)&hbuf,  g_h);
    cudaGetSymbolAddress((void**)&sprep, g_spre);
    cudaGetSymbolAddress((void**)&gatep, g_gate);
    cudaGetSymbolAddress((void**)&prodp, g_prod);
    float* h0p = hbuf;
    float* h1p = hbuf + (size_t)NN * HH;

    cudaFuncSetAttribute(gemm64k, cudaFuncAttributeMaxDynamicSharedMemorySize, GEMM_SMEM);

    // CSR over dst (built once; reused across layers)
    zerodeg_k<<<(NN + 255) / 256, 256>>>();
    hist_k<<<(EE + 255) / 256, 256>>>(ei);
    scan_k<<<1, 1024>>>();
    fill_k<<<(EE + 255) / 256, 256>>>(ei, et);

    // input projection: h0 = relu(x @ W_in^T + b_in)
    gemm64k<<<dim3((NN + 127) / 128, 1), 128, GEMM_SMEM>>>(x, 64, W_in, b_in, h0p, 64, NN, 0, 1, 0);

    float* hc = h0p;
    float* hn = h1p;
    for (int layer = 0; layer < LL; layer++) {
        // gate = sigmoid(h @ W_gate^T + b_gate)
        gemm64k<<<dim3((NN + 127) / 128, 8), 128, GEMM_SMEM>>>(hc, 64, W_gate, b_gate, gatep, 512, NN, 0, 2, 0);
        attproj_k<<<(NN + 15) / 16, 256>>>(hc, W_att);
        scoreexp_k<<<(EE + 255) / 256, 256>>>(ei, et, b_att);
        aggscatter_k<<<(NN + 7) / 8, 256>>>(hc);
        // prod[n,r,:] = gate[n,r,:] * (spre[n,r,:] @ W_rel[r]^T)
        gemm64k<<<dim3((NN + 127) / 128, 8), 128, GEMM_SMEM>>>(sprep, 512, W_rel, nullptr, prodp, 512, NN, 1, 0, 1);
        combine_k<<<(NN + 7) / 8, 256>>>(hc, hn, ln_g + layer * 64, ln_b + layer * 64);
        float* tmp = hc; hc = hn; hn = tmp;
    }

    gemm64k<<<dim3((NN + 127) / 128, 1), 128, GEMM_SMEM>>>(hc, 64, W_out, b_out, out, 64, NN, 0, 0, 0);
}